// round 6
// baseline (speedup 1.0000x reference)
#include <cuda_runtime.h>
#include <cuda_bf16.h>
#include <cstdint>

// pred (N=8, V=3, C=24, T=8, H=128, W=128) fp32; mask (N,H,W) i32 {0,1};
// vq_0 (1,C) fp32. out = sum(|pred - vq0[c]| * (1-mask)) / (sum(1-mask)*V*C*T)
//
// Persistent single-wave grid (148 SMs x 8 blocks), dynamic tickets with
// DOUBLE-BUFFERED prefetch (1 barrier/tile, atomic latency overlapped) and
// JPER=16 tiles (half the ticket/barrier count of R3). 32-reg consume-as-
// you-go inner loop (empirically best: occ 8 blocks/SM beat reg-batched MLP).

#define CTOT    24
#define HW4     4096              // 128*128/4
#define NPLANE4 2359296           // V*C*T*HW/4
#define VCT     576
#define JPER    16
#define NTILES  4608              // 36 chunks * 8 n * 4096 hw4 / 256 threads
#define NBLOCKS 1184              // 148 SMs * 8

__device__ double              g_num;
__device__ unsigned long long  g_cnt;
__device__ unsigned            g_work;
__device__ unsigned            g_ticket;

__global__ void __launch_bounds__(256, 8)
fused_kernel(const float4* __restrict__ pred,
             const int4*   __restrict__ mask,
             const float*  __restrict__ vq0,
             float*        __restrict__ out) {
    __shared__ float vqtab[VCT];
    for (int i = threadIdx.x; i < VCT; i += 256) {
        int c = (i >> 3) % CTOT;          // vct = (v*C + c)*T + t
        vqtab[i] = vq0[c];
    }

    __shared__ unsigned tiles[2];
    if (threadIdx.x == 0)
        tiles[0] = atomicAdd(&g_work, 1u);
    __syncthreads();                      // also covers vqtab init

    float acc = 0.f;
    unsigned long long cnt = 0ull;

    unsigned phase = 0;
    for (;;) {
        unsigned t = tiles[phase];
        // prefetch next ticket; its store is ordered by the barrier at loop end
        if (threadIdx.x == 0)
            tiles[phase ^ 1u] = atomicAdd(&g_work, 1u);
        if (t >= NTILES) break;

        unsigned tid   = t * 256u + threadIdx.x;
        unsigned hw4   = tid & (HW4 - 1);
        unsigned n     = (tid >> 12) & 7u;
        unsigned chunk = tid >> 15;       // 0..35
        unsigned nhw   = tid & 32767u;

        int4 m = mask[nhw];
        float wx = (m.x == 0) ? 1.f : 0.f;
        float wy = (m.y == 0) ? 1.f : 0.f;
        float wz = (m.z == 0) ? 1.f : 0.f;
        float ww = (m.w == 0) ? 1.f : 0.f;
        cnt += (unsigned long long)((m.x == 0) + (m.y == 0) + (m.z == 0) + (m.w == 0)) * JPER;

        const float4* p  = pred + (size_t)n * NPLANE4 + (size_t)(chunk * JPER) * HW4 + hw4;
        const float*  vt = vqtab + chunk * JPER;

        #pragma unroll
        for (int j = 0; j < JPER; j++) {
            float4 q = p[(size_t)j * HW4];
            float v = vt[j];
            acc = fmaf(fabsf(q.x - v), wx, acc);
            acc = fmaf(fabsf(q.y - v), wy, acc);
            acc = fmaf(fabsf(q.z - v), wz, acc);
            acc = fmaf(fabsf(q.w - v), ww, acc);
        }

        __syncthreads();                  // tiles[phase^1] visible; tiles[phase] free
        phase ^= 1u;
    }

    // block reduce
    #pragma unroll
    for (int off = 16; off; off >>= 1) {
        acc += __shfl_xor_sync(0xFFFFFFFFu, acc, off);
        cnt += __shfl_xor_sync(0xFFFFFFFFu, cnt, off);
    }
    __shared__ float              warp_sum[8];
    __shared__ unsigned long long warp_cnt[8];
    int lane = threadIdx.x & 31, wid = threadIdx.x >> 5;
    if (lane == 0) { warp_sum[wid] = acc; warp_cnt[wid] = cnt; }
    __syncthreads();

    __shared__ bool is_last;
    if (threadIdx.x == 0) {
        float s = 0.f;
        unsigned long long k = 0ull;
        #pragma unroll
        for (int w = 0; w < 8; w++) { s += warp_sum[w]; k += warp_cnt[w]; }
        atomicAdd(&g_num, (double)s);
        atomicAdd(&g_cnt, k);
        __threadfence();
        unsigned tk = atomicInc(&g_ticket, NBLOCKS - 1);
        is_last = (tk == NBLOCKS - 1);
    }
    __syncthreads();

    if (is_last && threadIdx.x == 0) {
        __threadfence();
        double num = *((volatile double*)&g_num);
        unsigned long long den = *((volatile unsigned long long*)&g_cnt);
        out[0] = (float)(num / (double)den);
        // reset for next graph replay (g_ticket already wrapped to 0).
        // Safe: every block has issued its final atomicAdd(&g_work) before
        // its completion ticket, so resetting g_work here cannot race.
        g_num  = 0.0;
        g_cnt  = 0ull;
        g_work = 0u;
        __threadfence();
    }
}

extern "C" void kernel_launch(void* const* d_in, const int* in_sizes, int n_in,
                              void* d_out, int out_size) {
    const float4* pred = (const float4*)d_in[0];
    const int4*   mask = (const int4*)d_in[1];
    const float*  vq0  = (const float*)d_in[2];
    float* out = (float*)d_out;

    fused_kernel<<<NBLOCKS, 256>>>(pred, mask, vq0, out);
}

// round 7
// speedup vs baseline: 1.0491x; 1.0491x over previous
#include <cuda_runtime.h>
#include <cuda_bf16.h>
#include <cstdint>

// pred (N=8, V=3, C=24, T=8, H=128, W=128) fp32; mask (N,H,W) i32 {0,1};
// vq_0 (1,C) fp32. out = sum(|pred - vq0[c]| * (1-mask)) / (sum(1-mask)*V*C*T)
//
// R3 structure (best: 49.6us) + cache-policy hints:
//   pred: __ldcs (evict-first — 302MB streamed once, don't thrash L2/L1)
//   mask: __ldg  (read-only, stays L2-resident for its 72x reuse)
// Persistent single-wave grid (148 SMs x 8 blocks), dynamic tile tickets,
// 9216 tiles of 256 threads x (1 mask int4 + 8 pred float4 @ stride HW4).
// Last block finalizes and resets globals for graph-replay determinism.

#define CTOT    24
#define HW4     4096              // 128*128/4
#define NPLANE4 2359296           // V*C*T*HW/4
#define VCT     576
#define JPER    8
#define NTILES  9216              // 72 chunks * 8 n * 4096 hw4 / 256 threads
#define NBLOCKS 1184              // 148 SMs * 8

__device__ double              g_num;
__device__ unsigned long long  g_cnt;
__device__ unsigned            g_work;
__device__ unsigned            g_ticket;

__global__ void __launch_bounds__(256, 8)
fused_kernel(const float4* __restrict__ pred,
             const int4*   __restrict__ mask,
             const float*  __restrict__ vq0,
             float*        __restrict__ out) {
    __shared__ float vqtab[VCT];
    for (int i = threadIdx.x; i < VCT; i += 256) {
        int c = (i >> 3) % CTOT;          // vct = (v*C + c)*T + t
        vqtab[i] = vq0[c];
    }

    __shared__ unsigned cur_tile;
    float acc = 0.f;
    unsigned long long cnt = 0ull;

    for (;;) {
        __syncthreads();                  // protect cur_tile reuse (covers vqtab init)
        if (threadIdx.x == 0)
            cur_tile = atomicAdd(&g_work, 1u);
        __syncthreads();
        unsigned t = cur_tile;
        if (t >= NTILES) break;

        unsigned tid   = t * 256u + threadIdx.x;
        unsigned hw4   = tid & (HW4 - 1);
        unsigned n     = (tid >> 12) & 7u;
        unsigned chunk = tid >> 15;       // 0..71
        unsigned nhw   = tid & 32767u;

        int4 m = __ldg(&mask[nhw]);
        float wx = (m.x == 0) ? 1.f : 0.f;
        float wy = (m.y == 0) ? 1.f : 0.f;
        float wz = (m.z == 0) ? 1.f : 0.f;
        float ww = (m.w == 0) ? 1.f : 0.f;
        cnt += (unsigned long long)((m.x == 0) + (m.y == 0) + (m.z == 0) + (m.w == 0)) * JPER;

        const float4* p  = pred + (size_t)n * NPLANE4 + (size_t)(chunk * JPER) * HW4 + hw4;
        const float*  vt = vqtab + chunk * JPER;

        #pragma unroll
        for (int j = 0; j < JPER; j++) {
            float4 q = __ldcs(&p[(size_t)j * HW4]);   // streaming: evict-first
            float v = vt[j];
            acc = fmaf(fabsf(q.x - v), wx, acc);
            acc = fmaf(fabsf(q.y - v), wy, acc);
            acc = fmaf(fabsf(q.z - v), wz, acc);
            acc = fmaf(fabsf(q.w - v), ww, acc);
        }
    }

    // block reduce
    #pragma unroll
    for (int off = 16; off; off >>= 1) {
        acc += __shfl_xor_sync(0xFFFFFFFFu, acc, off);
        cnt += __shfl_xor_sync(0xFFFFFFFFu, cnt, off);
    }
    __shared__ float              warp_sum[8];
    __shared__ unsigned long long warp_cnt[8];
    int lane = threadIdx.x & 31, wid = threadIdx.x >> 5;
    if (lane == 0) { warp_sum[wid] = acc; warp_cnt[wid] = cnt; }
    __syncthreads();

    __shared__ bool is_last;
    if (threadIdx.x == 0) {
        float s = 0.f;
        unsigned long long k = 0ull;
        #pragma unroll
        for (int w = 0; w < 8; w++) { s += warp_sum[w]; k += warp_cnt[w]; }
        atomicAdd(&g_num, (double)s);
        atomicAdd(&g_cnt, k);
        __threadfence();
        unsigned tk = atomicInc(&g_ticket, NBLOCKS - 1);
        is_last = (tk == NBLOCKS - 1);
    }
    __syncthreads();

    if (is_last && threadIdx.x == 0) {
        __threadfence();
        double num = *((volatile double*)&g_num);
        unsigned long long den = *((volatile unsigned long long*)&g_cnt);
        out[0] = (float)(num / (double)den);
        // reset for next graph replay (g_ticket already wrapped to 0)
        g_num  = 0.0;
        g_cnt  = 0ull;
        g_work = 0u;
        __threadfence();
    }
}

extern "C" void kernel_launch(void* const* d_in, const int* in_sizes, int n_in,
                              void* d_out, int out_size) {
    const float4* pred = (const float4*)d_in[0];
    const int4*   mask = (const int4*)d_in[1];
    const float*  vq0  = (const float*)d_in[2];
    float* out = (float*)d_out;

    fused_kernel<<<NBLOCKS, 256>>>(pred, mask, vq0, out);
}